// round 8
// baseline (speedup 1.0000x reference)
#include <cuda_runtime.h>
#include <cstdint>

// ---------------------------------------------------------------------------
// SparseResUQueryNet R8: brick-bitmap neighborhoods + hit compaction.
//
// Linear keys (for the H1 feature hash only): 28-bit
//   ((t*256+x)*256+y)*256+z, t<16, coords in [1,250] (no byte carry on +-1).
//
// Occupancy bitmaps use a BRICK layout: one uint32 covers a 4x4x2 voxel
// block, bit = (x&3)<<3 | (y&3)<<1 | (z&1); word index =
//   ((hi*64 + (x>>2))*64 + (y>>2))*128 + (z>>1)      (hi = t or b)
// A 3x3x3 neighborhood always lies inside the 2x2x2 surrounding words ->
// mask27 costs 8 loads (~4 sectors) instead of 18 loads (~9 sectors).
//
// Pooled rows are indexed by rank2(pk) = prefix-popcount over the bm2 brick
// words (rank is just a bijection; word order is irrelevant).
// Contested pool cells (~1%) are detected at insert, rows pre-zeroed, pooled
// via order-preserving-uint atomicMax, decoded on read.
// ---------------------------------------------------------------------------

#define FULL_MASK 0xFFFFFFFFu
#define H1_LOG 21
#define H1_SIZE (1u << H1_LOG)
#define H1_MASK (H1_SIZE - 1u)
#define EMPTY_KEY 0xFFFFFFFFu
#define BM1_WORDS (1u << 23)         // 16*64*64*128 = 8M words = 32 MB
#define BM2_WORDS (1u << 20)         // 2*64*64*128  = 1M words = 4 MB
#define CHUNK2 4096
#define NBLK2 (BM2_WORDS / CHUNK2)   // 256
#define NMAX  (1u << 20)

__device__ unsigned g_h1_keys[H1_SIZE];               // 8 MB
__device__ float    g_h1_feat[H1_SIZE];               // 8 MB
__device__ unsigned g_bm1[BM1_WORDS];                 // 32 MB brick bitmap
__device__ unsigned g_bm2[BM2_WORDS];                 // 4 MB brick bitmap
__device__ unsigned g_cont[BM2_WORDS];                // 4 MB contested bits
__device__ unsigned g_pref2[BM2_WORDS];               // 4 MB word prefix
__device__ unsigned g_bsum2[NBLK2];
__device__ unsigned g_maskH[NMAX];                    // 4 MB
__device__ int      g_rowOf[NMAX];                    // 4 MB rank2 | cont<<31
__device__ float    g_pooled[(size_t)NMAX * 32];      // 128 MB
__device__ int      g_worklist[NMAX * 2];             // 8 MB
__device__ unsigned g_maskQ[NMAX * 2];                // 8 MB
__device__ int      g_wl_cnt;

// Linear-key deltas (H1 probes only): (dx<<16)+(dy<<8)+dz, d=(dx+1)*9+(dy+1)*3+(dz+1)
__constant__ unsigned c_delta[27] = {
    0xFFFEFEFFu, 0xFFFEFF00u, 0xFFFEFF01u,
    0xFFFEFFFFu, 0xFFFF0000u, 0xFFFF0001u,
    0xFFFF00FFu, 0xFFFF0100u, 0xFFFF0101u,
    0xFFFFFEFFu, 0xFFFFFF00u, 0xFFFFFF01u,
    0xFFFFFFFFu, 0x00000000u, 0x00000001u,
    0x000000FFu, 0x00000100u, 0x00000101u,
    0x0000FEFFu, 0x0000FF00u, 0x0000FF01u,
    0x0000FFFFu, 0x00010000u, 0x00010001u,
    0x000100FFu, 0x00010100u, 0x00010101u
};

__device__ __forceinline__ unsigned hash1(unsigned k) {
    return (k * 2654435761u) >> (32 - H1_LOG);
}
__device__ __forceinline__ unsigned encf(float f) {
    unsigned b = __float_as_uint(f);
    return b ^ (unsigned)(((int)b >> 31) | 0x80000000);
}
__device__ __forceinline__ float decf(unsigned u) {
    unsigned x = ((int)u < 0) ? (u ^ 0x80000000u) : ~u;
    return __uint_as_float(x);
}
// Brick word index / bit position.
__device__ __forceinline__ unsigned bw_idx(unsigned hi, int x, int y, int z) {
    return ((hi * 64u + (unsigned)(x >> 2)) * 64u + (unsigned)(y >> 2)) * 128u +
           (unsigned)(z >> 1);
}
__device__ __forceinline__ unsigned bw_bit(int x, int y, int z) {
    return (unsigned)(((x & 3) << 3) | ((y & 3) << 1) | (z & 1));
}
// 27-neighbor occupancy mask from brick bitmap: 8 loads + compress ALU.
// mask bit d = (dx+1)*9 + (dy+1)*3 + (dz+1).
__device__ __forceinline__ unsigned mask27_brick(const unsigned* __restrict__ bm,
                                                 unsigned hi, int x, int y, int z) {
    int X0 = (x - 1) >> 2, Y0 = (y - 1) >> 2, Z0 = (z - 1) >> 1;
    unsigned base = ((hi * 64u + (unsigned)X0) * 64u + (unsigned)Y0) * 128u +
                    (unsigned)Z0;
    unsigned w000 = bm[base],        w001 = bm[base + 1];
    unsigned w010 = bm[base + 128],  w011 = bm[base + 129];
    unsigned w100 = bm[base + 8192], w101 = bm[base + 8193];
    unsigned w110 = bm[base + 8320], w111 = bm[base + 8321];
    int a = (x - 1) & 3;
    unsigned mask = 0;
#pragma unroll
    for (int dy = -1; dy <= 1; dy++) {
        int yy = y + dy;
        int iy = (yy >> 2) - Y0;  // 0 or 1
#pragma unroll
        for (int dz = -1; dz <= 1; dz++) {
            int zz = z + dz;
            int iz = (zz >> 1) - Z0;  // 0 or 1
            unsigned s = (unsigned)(((yy & 3) << 1) | (zz & 1));
            unsigned wl = iy ? (iz ? w011 : w010) : (iz ? w001 : w000);
            unsigned wh = iy ? (iz ? w111 : w110) : (iz ? w101 : w100);
            // 4 x-slot bits (stride 8) -> nibble via multiply-compress.
            unsigned t0 = (wl >> s) & 0x01010101u;
            unsigned t1 = (wh >> s) & 0x01010101u;
            unsigned xb = ((t0 * 0x01020408u) >> 24) |
                          ((((t1 * 0x01020408u) >> 24) & 0xFu) << 4);
            unsigned tri = (xb >> a) & 7u;  // bits: dx=-1,0,+1
            int d0 = (dy + 1) * 3 + (dz + 1);
            mask |= (tri & 1u) << d0;
            mask |= ((tri >> 1) & 1u) << (d0 + 9);
            mask |= ((tri >> 2) & 1u) << (d0 + 18);
        }
    }
    return mask;
}
__device__ __forceinline__ unsigned rank2_of(unsigned w, unsigned bit) {
    return g_pref2[w] + __popc(g_bm2[w] & ((1u << bit) - 1u));
}
__device__ __forceinline__ int nth_bit(unsigned mask, int lane) {
    unsigned mm = mask;
    for (int t = 0; t < lane; t++) mm &= mm - 1;
    return __ffs(mm) - 1;
}

// K0 -------------------------------------------------------------------------
__global__ void k_reset(const int4* __restrict__ hcoord,
                        const int* __restrict__ hbatch, int n) {
    int i = blockIdx.x * blockDim.x + threadIdx.x;
    int stride = gridDim.x * blockDim.x;
    for (unsigned s = (unsigned)i; s < H1_SIZE; s += stride)
        g_h1_keys[s] = EMPTY_KEY;
    if (i == 0) g_wl_cnt = 0;
    if (i >= n) return;
    int4 c = hcoord[i];  // t, x, y, z
    unsigned w1 = bw_idx((unsigned)c.x, c.y, c.z, c.w);
    unsigned w2 = bw_idx((unsigned)hbatch[i], c.y, c.z, c.w);
    g_bm1[w1] = 0u;
    g_bm2[w2] = 0u;
    g_cont[w2] = 0u;
}

// K1 -------------------------------------------------------------------------
__global__ void k_insert(const float* __restrict__ hfeat,
                         const int4* __restrict__ hcoord,
                         const int* __restrict__ hbatch, int n) {
    int i = blockIdx.x * blockDim.x + threadIdx.x;
    if (i >= n) return;
    int4 c = hcoord[i];
    unsigned bit = 1u << bw_bit(c.y, c.z, c.w);
    atomicOr(&g_bm1[bw_idx((unsigned)c.x, c.y, c.z, c.w)], bit);
    unsigned key = ((unsigned)c.x << 24) | ((unsigned)c.y << 16) |
                   ((unsigned)c.z << 8) | (unsigned)c.w;
    unsigned s = hash1(key);
    while (true) {  // history keys unique (np.unique upstream)
        unsigned old = atomicCAS(&g_h1_keys[s], EMPTY_KEY, key);
        if (old == EMPTY_KEY) { g_h1_feat[s] = hfeat[i]; break; }
        s = (s + 1) & H1_MASK;
    }
    unsigned w2 = bw_idx((unsigned)hbatch[i], c.y, c.z, c.w);
    unsigned prev = atomicOr(&g_bm2[w2], bit);
    if (prev & bit) atomicOr(&g_cont[w2], bit);
}

// bm2 prefix scan (2 passes; pass B fused into C) ------------------------------
__global__ void k_scanA() {
    int blk = blockIdx.x, tid = threadIdx.x;
    const uint4* bm = (const uint4*)g_bm2;
    size_t w4 = (size_t)blk * (CHUNK2 / 4) + (size_t)tid * 4;
    int s = 0;
#pragma unroll
    for (int j = 0; j < 4; j++) {
        uint4 v = bm[w4 + j];
        s += __popc(v.x) + __popc(v.y) + __popc(v.z) + __popc(v.w);
    }
    __shared__ int sh[256];
    sh[tid] = s;
    __syncthreads();
    for (int off = 128; off; off >>= 1) {
        if (tid < off) sh[tid] += sh[tid + off];
        __syncthreads();
    }
    if (tid == 0) g_bsum2[blk] = (unsigned)sh[0];
}
__global__ void k_scanC() {
    int blk = blockIdx.x, tid = threadIdx.x;
    __shared__ int sh[256];
    // fused pass B: chunk_base = sum of bsum2[j] for j < blk
    sh[tid] = (tid < blk) ? (int)g_bsum2[tid] : 0;
    __syncthreads();
    for (int off = 128; off; off >>= 1) {
        if (tid < off) sh[tid] += sh[tid + off];
        __syncthreads();
    }
    unsigned chunk_base = (unsigned)sh[0];
    __syncthreads();
    // per-word exclusive prefix within chunk
    size_t w0 = (size_t)blk * CHUNK2 + (size_t)tid * 16;
    unsigned wv[16];
    int s = 0;
#pragma unroll
    for (int j = 0; j < 16; j++) { wv[j] = g_bm2[w0 + j]; s += __popc(wv[j]); }
    sh[tid] = s;
    __syncthreads();
    for (int off = 1; off < 256; off <<= 1) {
        int add = (tid >= off) ? sh[tid - off] : 0;
        __syncthreads();
        sh[tid] += add;
        __syncthreads();
    }
    unsigned run = chunk_base + (unsigned)(sh[tid] - s);
#pragma unroll
    for (int j = 0; j < 16; j++) { g_pref2[w0 + j] = run; run += __popc(wv[j]); }
}

// K2: thread per voxel ---------------------------------------------------------
__global__ void k_maskH(const int4* __restrict__ hcoord,
                        const int* __restrict__ hbatch, int n) {
    int i = blockIdx.x * blockDim.x + threadIdx.x;
    if (i >= n) return;
    int4 c = hcoord[i];
    g_maskH[i] = mask27_brick(g_bm1, (unsigned)c.x, c.y, c.z, c.w);
    unsigned w2 = bw_idx((unsigned)hbatch[i], c.y, c.z, c.w);
    unsigned bit = bw_bit(c.y, c.z, c.w);
    unsigned r2 = rank2_of(w2, bit);
    bool cont = (g_cont[w2] >> bit) & 1u;
    g_rowOf[i] = (int)(r2 | (cont ? 0x80000000u : 0u));
    if (cont) {
        float* r = &g_pooled[(size_t)r2 * 32];
#pragma unroll
        for (int q = 0; q < 32; q++) r[q] = 0.0f;  // bits 0 = encoded minimum
    }
}

// K3: warp per voxel -------------------------------------------------------------
__global__ void __launch_bounds__(256)
k_bb_pool(const float* __restrict__ hfeat,
          const float* __restrict__ Wbb,
          const int4* __restrict__ hcoord, int n) {
    int w = (int)((blockIdx.x * blockDim.x + threadIdx.x) >> 5);
    int lane = threadIdx.x & 31;
    if (w >= n) return;
    unsigned mask = g_maskH[w];   // broadcast
    int rw = g_rowOf[w];          // broadcast
    unsigned row = (unsigned)rw & 0x7FFFFFFFu;
    bool cont = rw < 0;
    float acc;
    if (mask == (1u << 13)) {     // self-only: dominant fast path (~93%)
        acc = hfeat[w] * Wbb[13 * 32 + lane];
    } else {
        int4 c = hcoord[w];       // broadcast (L2-hot)
        unsigned key = ((unsigned)c.x << 24) | ((unsigned)c.y << 16) |
                       ((unsigned)c.z << 8) | (unsigned)c.w;
        int nhit = __popc(mask);
        float f = 0.0f;
        int d = 0;
        if (lane < nhit) {
            d = nth_bit(mask, lane);
            if (d == 13) {
                f = hfeat[w];
            } else {
                unsigned nk = key + c_delta[d];
                unsigned s = hash1(nk);
                while (g_h1_keys[s] != nk) s = (s + 1) & H1_MASK;  // present
                f = g_h1_feat[s];
            }
        }
        acc = 0.0f;
        for (int i = 0; i < nhit; i++) {  // ascending d == reference order
            float fd = __shfl_sync(FULL_MASK, f, i);
            int di = __shfl_sync(FULL_MASK, d, i);
            acc = fmaf(fd, Wbb[di * 32 + lane], acc);
        }
    }
    float* addr = &g_pooled[(size_t)row * 32 + lane];  // coalesced 128B
    if (cont) atomicMax((unsigned*)addr, encf(acc));
    else *addr = acc;
}

// K4: thread per query point -------------------------------------------------------
__global__ void k_maskQ(const float* __restrict__ points,
                        const int4* __restrict__ qcoord,
                        float* __restrict__ out, int npts) {
    int p = blockIdx.x * blockDim.x + threadIdx.x;
    bool active = p < npts;
    unsigned mask = 0;
    if (active) {
        int4 c = qcoord[p];  // b, x, y, z
        mask = mask27_brick(g_bm2, (unsigned)c.x, c.y, c.z, c.w);
        g_maskQ[p] = mask;
    }
    bool hit = active && (mask != 0u);
    unsigned bal = __ballot_sync(FULL_MASK, hit);
    if (hit) {  // warp-aggregated worklist append
        int lane = threadIdx.x & 31;
        int leader = __ffs(bal) - 1;
        int base = 0;
        if (lane == leader) base = atomicAdd(&g_wl_cnt, __popc(bal));
        base = __shfl_sync(bal, base, leader);
        g_worklist[base + __popc(bal & ((1u << lane) - 1u))] = p;
    }
    if (active && !mask) {  // finalize no-hit rows here (58%)
        float4* o = (float4*)(out + (size_t)p * 36);
        const float* pt = points + (size_t)p * 5;
        o[0] = make_float4(pt[0], pt[1], pt[2], pt[3]);
        float4 z = make_float4(0.f, 0.f, 0.f, 0.f);
#pragma unroll
        for (int q = 1; q < 9; q++) o[q] = z;
    }
}

// K5: warp per HIT query point --------------------------------------------------
__global__ void __launch_bounds__(256)
k_query(const float* __restrict__ points,
        const float* __restrict__ Wc,
        const int4* __restrict__ qcoord,
        float* __restrict__ out, int npts) {
    int widx = (int)((blockIdx.x * blockDim.x + threadIdx.x) >> 5);
    int lane = threadIdx.x & 31;
    int cnt = g_wl_cnt;
    if (widx >= cnt) return;
    int p = g_worklist[widx];
    unsigned mask = g_maskQ[p];  // broadcast
    int4 c = qcoord[p];          // broadcast
    int nhit = __popc(mask);
    int d = 0, row = 0;
    bool cont = false;
    if (lane < nhit) {
        d = nth_bit(mask, lane);
        int dx = d / 9 - 1, r9 = d % 9;
        int dy = r9 / 3 - 1, dz = r9 % 3 - 1;
        int xx = c.y + dx, yy = c.z + dy, zz = c.w + dz;
        unsigned wq = bw_idx((unsigned)c.x, xx, yy, zz);
        unsigned bit = bw_bit(xx, yy, zz);
        row = (int)rank2_of(wq, bit);
        cont = (g_cont[wq] >> bit) & 1u;
    }
    float acc = 0.0f;
    for (int i = 0; i < nhit; i++) {  // ascending d == reference order
        int rowi = __shfl_sync(FULL_MASK, row, i);
        int di = __shfl_sync(FULL_MASK, d, i);
        int conti = __shfl_sync(FULL_MASK, (int)cont, i);
        const float4* prow = (const float4*)&g_pooled[(size_t)rowi * 32];
        const float* wb = Wc + di * 1024 + lane;
#pragma unroll
        for (int q = 0; q < 8; q++) {
            float4 v = prow[q];  // uniform address -> broadcast
            if (conti) {
                v.x = decf(__float_as_uint(v.x));
                v.y = decf(__float_as_uint(v.y));
                v.z = decf(__float_as_uint(v.z));
                v.w = decf(__float_as_uint(v.w));
            }
            acc = fmaf(v.x, wb[(q * 4 + 0) * 32], acc);
            acc = fmaf(v.y, wb[(q * 4 + 1) * 32], acc);
            acc = fmaf(v.z, wb[(q * 4 + 2) * 32], acc);
            acc = fmaf(v.w, wb[(q * 4 + 3) * 32], acc);
        }
    }
    float* o = out + (size_t)p * 36;
    o[4 + lane] = acc;
    if (lane < 4) o[lane] = points[(size_t)p * 5 + lane];
}

// ---------------------------------------------------------------------------
extern "C" void kernel_launch(void* const* d_in, const int* in_sizes, int n_in,
                              void* d_out, int out_size) {
    const float* hfeat  = (const float*)d_in[0];
    const float* points = (const float*)d_in[1];
    const float* Wbb    = (const float*)d_in[2];
    const float* Wc     = (const float*)d_in[3];
    const int4*  hcoord = (const int4*)d_in[4];
    const int*   hbatch = (const int*)d_in[5];
    const int4*  qcoord = (const int4*)d_in[6];
    float* out = (float*)d_out;

    int n    = in_sizes[5];      // history voxel count
    int npts = in_sizes[6] / 4;  // query point count

    const int TB = 256;
    int nb  = (n + TB - 1) / TB;
    int qb  = (npts + TB - 1) / TB;
    int clr = ((int)H1_SIZE > n ? (int)H1_SIZE : n);
    k_reset<<<(clr + TB - 1) / TB, TB>>>(hcoord, hbatch, n);
    k_insert<<<nb, TB>>>(hfeat, hcoord, hbatch, n);
    k_scanA<<<NBLK2, TB>>>();
    k_scanC<<<NBLK2, TB>>>();
    k_maskH<<<nb, TB>>>(hcoord, hbatch, n);
    {
        long long tw = (long long)n * 32;
        k_bb_pool<<<(int)((tw + TB - 1) / TB), TB>>>(hfeat, Wbb, hcoord, n);
    }
    k_maskQ<<<qb, TB>>>(points, qcoord, out, npts);
    {
        long long tw = (long long)npts * 32;  // worst case; excess warps exit
        k_query<<<(int)((tw + TB - 1) / TB), TB>>>(points, Wc, qcoord, out, npts);
    }
}